// round 17
// baseline (speedup 1.0000x reference)
#include <cuda_runtime.h>
#include <cuda_bf16.h>
#include <cstdint>

#define NPTS   8192
#define CH     32
#define TILE   256
#define MT     32                      // NPTS / TILE
#define NTILES 528                     // MT*(MT+1)/2 upper-triangle tile pairs
#define NPREP  128                     // prep blocks (8192 / 64)
#define LDPW   20                      // padded row stride in b32 words (80 bytes)

// ---------------- device scratch (no allocations allowed) -------------------
__device__ float    g_sq[NPTS];           // full 32-ch tree norms (exact path)
__device__ uint32_t g_xa[NPTS * 16];      // A-flavor rows: ch0..27, (-s28/2, 1), (0,0)
__device__ uint32_t g_xb[NPTS * 16];      // B-flavor rows: ch0..27, (1, -s28/2), (0,0)
__device__ float    g_partial[NTILES];
__device__ float    g_diagpart[NPREP];
__device__ int      g_counter;            // zero-init; reset by last CTA

// ---------------------------------------------------------------------------
// Kernel A (prep): smem-staged COALESCED loads; per-point arithmetic is
// bit-identical to every passing round (tree sq vs sequential-FMA self-dot
// -> reference-matching diagonal loss), plus A/B-flavor bf16 packs with the
// norm-augmentation channels.
// ---------------------------------------------------------------------------
__global__ __launch_bounds__(64) void prep_kernel(const float* __restrict__ x) {
    __shared__ float    xs[CH][65];     // 8.3 KB, padded banks
    __shared__ uint32_t stA[64 * 16];   // 4 KB
    __shared__ uint32_t stB[64 * 16];   // 4 KB
    __shared__ float    red[64];

    int tid = threadIdx.x;
    int base = blockIdx.x * 64;

    // coalesced: each channel row is 64 consecutive floats
#pragma unroll
    for (int c = 0; c < CH; ++c) xs[c][tid] = x[c * NPTS + base + tid];
    __syncthreads();

    float v[CH];
#pragma unroll
    for (int c = 0; c < CH; ++c) v[c] = xs[c][tid];

    // sq: non-FMA rounded products, 4-accumulator tree (XLA-reduce flavor)
    float a0 = 0.f, a1 = 0.f, a2 = 0.f, a3 = 0.f;
#pragma unroll
    for (int c = 0; c < CH; c += 4) {
        a0 = __fadd_rn(a0, __fmul_rn(v[c + 0], v[c + 0]));
        a1 = __fadd_rn(a1, __fmul_rn(v[c + 1], v[c + 1]));
        a2 = __fadd_rn(a2, __fmul_rn(v[c + 2], v[c + 2]));
        a3 = __fadd_rn(a3, __fmul_rn(v[c + 3], v[c + 3]));
    }
    float sq = __fadd_rn(__fadd_rn(a0, a1), __fadd_rn(a2, a3));
    g_sq[base + tid] = sq;

    // self-dot: sequential FMA chain (GEMM flavor) -> diagonal noise d2 ~ +-eps
    float dot = 0.f;
#pragma unroll
    for (int c = 0; c < CH; ++c) dot = fmaf(v[c], v[c], dot);

    float d2 = fmaf(-2.f, dot, __fadd_rn(sq, sq));
    float f = 0.f;
    if (d2 < 4.f) {
        d2 = fmaxf(d2, 0.f);
        float d = sqrtf(d2);
        f = fmaf(1.5f, d, fmaf(-0.5f, d2, -1.f));
    }

    // 28-channel screen norm (fp32)
    float s28 = 0.f;
#pragma unroll
    for (int c = 0; c < 28; ++c) s28 = fmaf(v[c], v[c], s28);
    float nh = -0.5f * s28;

    // data words 0..13 (channels 0..27), augmentation words 14..15
#pragma unroll
    for (int w = 0; w < 14; ++w) {
        __nv_bfloat162 pk = __floats2bfloat162_rn(v[2 * w], v[2 * w + 1]);
        uint32_t u = *reinterpret_cast<uint32_t*>(&pk);
        stA[tid * 16 + w] = u;
        stB[tid * 16 + w] = u;
    }
    {
        __nv_bfloat162 pa = __floats2bfloat162_rn(nh, 1.0f);   // A: ch28=-s/2, ch29=1
        __nv_bfloat162 pb = __floats2bfloat162_rn(1.0f, nh);   // B: ch28=1, ch29=-s/2
        stA[tid * 16 + 14] = *reinterpret_cast<uint32_t*>(&pa);
        stB[tid * 16 + 14] = *reinterpret_cast<uint32_t*>(&pb);
        stA[tid * 16 + 15] = 0u;
        stB[tid * 16 + 15] = 0u;
    }
    __syncthreads();
    uint32_t* dstA = &g_xa[blockIdx.x * 64 * 16];
    uint32_t* dstB = &g_xb[blockIdx.x * 64 * 16];
#pragma unroll
    for (int i = tid; i < 1024; i += 64) {
        dstA[i] = stA[i];
        dstB[i] = stB[i];
    }

    // deterministic block reduction of diagonal contributions
    red[tid] = f;
    __syncthreads();
#pragma unroll
    for (int s = 32; s > 0; s >>= 1) {
        if (tid < s) red[tid] += red[tid + s];
        __syncthreads();
    }
    if (tid == 0) g_diagpart[blockIdx.x] = red[0];
}

// ---------------------------------------------------------------------------
// PTX helpers (all sm_80/75+ baseline; portable to plain sm_103).
// ---------------------------------------------------------------------------
__device__ __forceinline__ void hmma16816(float* c, const uint32_t* a, const uint32_t* b) {
    asm volatile(
        "mma.sync.aligned.m16n8k16.row.col.f32.bf16.bf16.f32 "
        "{%0,%1,%2,%3}, {%4,%5,%6,%7}, {%8,%9}, {%0,%1,%2,%3};"
        : "+f"(c[0]), "+f"(c[1]), "+f"(c[2]), "+f"(c[3])
        : "r"(a[0]), "r"(a[1]), "r"(a[2]), "r"(a[3]), "r"(b[0]), "r"(b[1]));
}

__device__ __forceinline__ void ldsm_x4(uint32_t& r0, uint32_t& r1,
                                        uint32_t& r2, uint32_t& r3, uint32_t addr) {
    asm volatile("ldmatrix.sync.aligned.m8n8.x4.shared.b16 {%0,%1,%2,%3}, [%4];"
                 : "=r"(r0), "=r"(r1), "=r"(r2), "=r"(r3) : "r"(addr));
}

// ---------------------------------------------------------------------------
// Exact fp32 recompute of one pair (full 32 channels, reference formula).
// ---------------------------------------------------------------------------
__device__ __noinline__ float exact_pair(const float* __restrict__ x, int gi, int gj) {
    float dt = 0.f;
#pragma unroll
    for (int c = 0; c < CH; ++c)
        dt = fmaf(x[c * NPTS + gi], x[c * NPTS + gj], dt);
    float e2 = fmaf(-2.f, dt, g_sq[gi] + g_sq[gj]);
    if (e2 < 4.f) {
        e2 = fmaxf(e2, 0.f);
        float d = sqrtf(e2);
        return fmaf(1.5f, d, fmaf(-0.5f, e2, -1.f));
    }
    return 0.f;
}

// ---------------------------------------------------------------------------
// Cold path: lane-exact fp32 recompute of this lane's 8 rows x 32 cols.
// Skips gi==gj (diagonal loss handled in prep).
// ---------------------------------------------------------------------------
__device__ __noinline__ float slow_lane(const float* __restrict__ x,
                                        int I, int J, int m0, int n0,
                                        int qr, int qc) {
    float acc = 0.f;
#pragma unroll 1
    for (int r = 0; r < 8; ++r) {
        int gi = I * TILE + m0 + (r >> 1) * 16 + qr + (r & 1) * 8;
#pragma unroll 1
        for (int cidx = 0; cidx < 32; ++cidx) {
            int gj = J * TILE + n0 + (cidx >> 1) * 8 + 2 * qc + (cidx & 1);
            if (gi != gj) acc += exact_pair(x, gi, gj);
        }
    }
    return acc;
}

// ---------------------------------------------------------------------------
// Kernel B (tile): one CTA per (I,J) 256x256 tile pair, J >= I, 8 warps.
// K=32 bf16 HMMA with norm augmentation: acc = dot28 - s28_i/2 - s28_j/2;
// screen flag iff acc > -3 (sound: d2_full < 4 ==> acc > -3).
// LDSM x4 loads: one per 2 njs for B, 4 total for A. Branch-free vmax loop
// for ALL tiles; diagonal tiles substitute -1e30 on gi==gj elements via SEL.
// Rare lane-level flag -> out-of-line exact recompute.
// Last CTA performs the deterministic final reduction.
// ---------------------------------------------------------------------------
__global__ __launch_bounds__(256, 4) void tile_kernel(const float* __restrict__ x,
                                                      float* __restrict__ out) {
    __shared__ __align__(16) uint32_t As[TILE * LDPW];   // 20 KB
    __shared__ __align__(16) uint32_t Bs[TILE * LDPW];   // 20 KB
    __shared__ float red[256];
    __shared__ bool  amlast;

    int tid = threadIdx.x;
    int wid = tid >> 5;
    int lane = tid & 31;

    // decode blockIdx -> (I, J) over upper triangle
    int bid = blockIdx.x;
    int I = 0, rem = bid;
    while (rem >= MT - I) { rem -= MT - I; ++I; }
    int J = I + rem;
    bool diag = (I == J);

    // fill A/B tiles: 256 threads, 2 tiles x 256 rows -> 2 rows per thread
    {
        int which = tid >> 7;                  // 0 -> A, 1 -> B
        int r0 = tid & 127;
        const uint32_t* gsrc = which ? g_xb : g_xa;
        int tilebase = (which ? J : I) * TILE;
#pragma unroll
        for (int rr = 0; rr < 2; ++rr) {
            int row = r0 + rr * 128;
            const uint4* src = reinterpret_cast<const uint4*>(&gsrc[(tilebase + row) * 16]);
            uint4* dst = reinterpret_cast<uint4*>((which ? Bs : As) + row * LDPW);
#pragma unroll
            for (int q = 0; q < 4; ++q) dst[q] = src[q];
        }
    }
    __syncthreads();

    int m0 = (wid & 3) * 64;     // row block of this warp (64 rows)
    int n0 = (wid >> 2) * 128;   // col block of this warp (128 cols)
    int qr = lane >> 2;          // 0..7
    int qc = lane & 3;           // 0..3

    // LDSM base addresses (derivation matches the R12-verified manual layout)
    uint32_t aBase = (uint32_t)__cvta_generic_to_shared(As) +
        (((m0 + ((lane >> 3) & 1) * 8 + (lane & 7)) * LDPW + (lane >> 4) * 4) * 4);
    uint32_t bBase = (uint32_t)__cvta_generic_to_shared(Bs) +
        (((n0 + (lane >> 4) * 8 + (lane & 7)) * LDPW + ((lane >> 3) & 1) * 4) * 4);

    // A fragments: one ldmatrix.x4 per 16-row slab
    uint32_t afr[4][4];
#pragma unroll
    for (int mi = 0; mi < 4; ++mi)
        ldsm_x4(afr[mi][0], afr[mi][1], afr[mi][2], afr[mi][3],
                aBase + mi * 16 * LDPW * 4);

    float vm0 = -1e30f, vm1 = -1e30f, vm2 = -1e30f, vm3 = -1e30f;

    if (!diag) {
        // ---- hot path: 8 nj-pairs, zero branches ----
#pragma unroll
        for (int p = 0; p < 8; ++p) {
            uint32_t b0, b1, b2, b3;
            ldsm_x4(b0, b1, b2, b3, bBase + p * 16 * LDPW * 4);
            uint32_t bf0[2] = {b0, b1};
            uint32_t bf1[2] = {b2, b3};
#pragma unroll
            for (int half = 0; half < 2; ++half) {
                const uint32_t* bf = half ? bf1 : bf0;
                float acc[4][4];
#pragma unroll
                for (int mi = 0; mi < 4; ++mi) {
                    acc[mi][0] = acc[mi][1] = acc[mi][2] = acc[mi][3] = 0.f;
                    hmma16816(acc[mi], afr[mi], bf);
                }
                vm0 = fmaxf(vm0, fmaxf(fmaxf(acc[0][0], acc[0][1]), fmaxf(acc[0][2], acc[0][3])));
                vm1 = fmaxf(vm1, fmaxf(fmaxf(acc[1][0], acc[1][1]), fmaxf(acc[1][2], acc[1][3])));
                vm2 = fmaxf(vm2, fmaxf(fmaxf(acc[2][0], acc[2][1]), fmaxf(acc[2][2], acc[2][3])));
                vm3 = fmaxf(vm3, fmaxf(fmaxf(acc[3][0], acc[3][1]), fmaxf(acc[3][2], acc[3][3])));
            }
        }
    } else {
        // ---- diagonal tile: same loop + SEL-exclusion of gi==gj elements ----
#pragma unroll
        for (int p = 0; p < 8; ++p) {
            uint32_t b0, b1, b2, b3;
            ldsm_x4(b0, b1, b2, b3, bBase + p * 16 * LDPW * 4);
            uint32_t bf0[2] = {b0, b1};
            uint32_t bf1[2] = {b2, b3};
#pragma unroll
            for (int half = 0; half < 2; ++half) {
                const uint32_t* bf = half ? bf1 : bf0;
                int colb = n0 + (2 * p + half) * 8 + 2 * qc;
                float acc[4][4];
#pragma unroll
                for (int mi = 0; mi < 4; ++mi) {
                    acc[mi][0] = acc[mi][1] = acc[mi][2] = acc[mi][3] = 0.f;
                    hmma16816(acc[mi], afr[mi], bf);
                    int row0 = m0 + mi * 16 + qr;
#pragma unroll
                    for (int e = 0; e < 4; ++e) {
                        int row = row0 + (e >> 1) * 8;
                        int col = colb + (e & 1);
                        if (row == col) acc[mi][e] = -1e30f;   // predicated SEL
                    }
                }
                vm0 = fmaxf(vm0, fmaxf(fmaxf(acc[0][0], acc[0][1]), fmaxf(acc[0][2], acc[0][3])));
                vm1 = fmaxf(vm1, fmaxf(fmaxf(acc[1][0], acc[1][1]), fmaxf(acc[1][2], acc[1][3])));
                vm2 = fmaxf(vm2, fmaxf(fmaxf(acc[2][0], acc[2][1]), fmaxf(acc[2][2], acc[2][3])));
                vm3 = fmaxf(vm3, fmaxf(fmaxf(acc[3][0], acc[3][1]), fmaxf(acc[3][2], acc[3][3])));
            }
        }
    }

    float vmax = fmaxf(fmaxf(vm0, vm1), fmaxf(vm2, vm3));
    float local = 0.f;
    if (vmax > -3.f)   // sound screen: d2_full < 4 ==> acc > -3
        local = slow_lane(x, I, J, m0, n0, qr, qc);
    if (!diag) local *= 2.f;   // symmetry: (I,J) and (J,I) identical

    // deterministic block reduction
    red[tid] = local;
    __syncthreads();
#pragma unroll
    for (int s = 128; s > 0; s >>= 1) {
        if (tid < s) red[tid] += red[tid + s];
        __syncthreads();
    }
    if (tid == 0) g_partial[bid] = red[0];

    // last CTA performs the deterministic final reduction
    if (tid == 0) {
        __threadfence();
        int prev = atomicAdd(&g_counter, 1);
        amlast = (prev == NTILES - 1);
    }
    __syncthreads();
    if (amlast) {
        float s = 0.f;
        for (int i = tid; i < NTILES; i += 256) s += g_partial[i];
        for (int i = tid; i < NPREP; i += 256) s += g_diagpart[i];
        red[tid] = s;
        __syncthreads();
#pragma unroll
        for (int k = 128; k > 0; k >>= 1) {
            if (tid < k) red[tid] += red[tid + k];
            __syncthreads();
        }
        if (tid == 0) {
            out[0] = 0.25f * red[0];
            g_counter = 0;           // reset for next graph replay
        }
    }
}

// ---------------------------------------------------------------------------
extern "C" void kernel_launch(void* const* d_in, const int* in_sizes, int n_in,
                              void* d_out, int out_size) {
    const float* x = (const float*)d_in[0];   // [1, 32, 8192] fp32, channel-major
    float* out = (float*)d_out;

    prep_kernel<<<NPREP, 64>>>(x);
    tile_kernel<<<NTILES, 256>>>(x, out);
}